// round 2
// baseline (speedup 1.0000x reference)
#include <cuda_runtime.h>
#include <math.h>

// Problem constants
#define Bn 16
#define Sn 2048
#define Dn 128
#define MY 64   // y rows per CTA
#define NX 64   // x cols per tile

// Scratch for sum-over-y of Y (for attention_visual). __device__ global: allowed.
__device__ float g_ysum[Bn * Dn];

// ---------------------------------------------------------------------------
// Zero-init: attention_out region of d_out + g_ysum (both 2048 floats)
// ---------------------------------------------------------------------------
__global__ void zero_kernel(float* __restrict__ outAttn) {
    int t = blockIdx.x * blockDim.x + threadIdx.x;
    if (t < Bn * Dn) {
        outAttn[t] = 0.f;
        g_ysum[t]  = 0.f;
    }
}

// ---------------------------------------------------------------------------
// Sum Y over the y-sequence: g_ysum[b][d] = sum_y Y[b][y][d]
// grid (16 chunks, 16 b), 128 threads (one per d). Coalesced loads.
// ---------------------------------------------------------------------------
__global__ void ysum_kernel(const float* __restrict__ Y) {
    int b = blockIdx.y;
    int chunk = blockIdx.x;
    int d = threadIdx.x;
    const float* base = Y + ((size_t)b * Sn + (size_t)chunk * 128) * Dn + d;
    float s = 0.f;
#pragma unroll 8
    for (int r = 0; r < 128; r++) s += base[(size_t)r * Dn];
    atomicAdd(&g_ysum[b * Dn + d], s);
}

// ---------------------------------------------------------------------------
// attention_visual[b][x] = dot(g_ysum[b], X[b][x]) / Sn
// grid (16 xchunks, 16 b), 128 threads, thread = one x row.
// ---------------------------------------------------------------------------
__global__ void visual_kernel(const float* __restrict__ X, float* __restrict__ outVis) {
    __shared__ float yb[Dn];
    int b = blockIdx.y;
    int chunk = blockIdx.x;
    int t = threadIdx.x;
    yb[t] = g_ysum[b * Dn + t];
    __syncthreads();

    int x = chunk * 128 + t;
    const float4* xr = (const float4*)(X + ((size_t)b * Sn + x) * Dn);
    const float4* yv = (const float4*)yb;
    float s = 0.f;
#pragma unroll
    for (int i = 0; i < Dn / 4; i++) {
        float4 a = xr[i];
        float4 c = yv[i];
        s += a.x * c.x + a.y * c.y + a.z * c.z + a.w * c.w;
    }
    outVis[(size_t)b * Sn + x] = s * (1.f / Sn);
}

// ---------------------------------------------------------------------------
// Main fused attention kernel.
// Per CTA: one 64-row y-tile of batch b. Loop over 32 x-tiles of 64:
//   GEMM1: S[64x64] = Yt . Xt        (register-tiled 4x4 per thread)
//   P = exp(S - 30)  (softmax shift constant; scores bounded ~|50|)
//   den[m] += row sums of P
//   GEMM2: num[64x128] += P . X      (register-tiled 4x8 per thread)
// Epilogue: out[b][d] += sum_m num[m][d]/den[m] / Sn (atomicAdd).
//
// Smem (floats): Yt[128][65] (Y^T), Xt[128][65] (X^T), Pt[64][65] (P^T), den[64]
// Padded stride 65 keeps scalar LDS conflict-free on the frag reads.
// ---------------------------------------------------------------------------
__global__ __launch_bounds__(256, 2)
void attn_kernel(const float* __restrict__ X, const float* __restrict__ Y,
                 float* __restrict__ outAttn) {
    extern __shared__ float sm[];
    float* Yt    = sm;                       // 128*65
    float* Xt    = sm + 128 * 65;            // 128*65
    float* Pt    = sm + 2 * 128 * 65;        // 64*65
    float* denSm = sm + 2 * 128 * 65 + 64 * 65;  // 64

    const int tid = threadIdx.x;
    const int tr = tid >> 4;    // 0..15 -> rows 4*tr..
    const int tc = tid & 15;    // 0..15 -> S cols 4*tc.. / d cols 8*tc..
    const int b = blockIdx.y;
    const int ybase = blockIdx.x * MY;

    // Load + transpose Y tile: Yt[k][m] = Y[ybase+m][k]
    {
        const float4* Yg = (const float4*)(Y + ((size_t)b * Sn + ybase) * Dn);
#pragma unroll
        for (int i = 0; i < 8; i++) {
            int e = tid + i * 256;        // 2048 float4 total
            int m = e >> 5;               // row within tile
            int c = e & 31;               // float4 index within row
            float4 v = Yg[e];
            float* p = Yt + (4 * c) * 65 + m;
            p[0] = v.x; p[65] = v.y; p[130] = v.z; p[195] = v.w;
        }
    }

    float num[4][8];
#pragma unroll
    for (int i = 0; i < 4; i++)
#pragma unroll
        for (int j = 0; j < 8; j++) num[i][j] = 0.f;
    float denAcc = 0.f;   // valid in tid<64 (row = tid)

    for (int xt = 0; xt < Sn / NX; xt++) {
        __syncthreads();  // prev GEMM2/den done with Xt/Pt (also covers Yt on first iter)

        // Load + transpose X tile: Xt[k][n] = X[xt*NX+n][k]
        {
            const float4* Xg = (const float4*)(X + ((size_t)b * Sn + (size_t)xt * NX) * Dn);
#pragma unroll
            for (int i = 0; i < 8; i++) {
                int e = tid + i * 256;
                int m = e >> 5;
                int c = e & 31;
                float4 v = Xg[e];
                float* p = Xt + (4 * c) * 65 + m;
                p[0] = v.x; p[65] = v.y; p[130] = v.z; p[195] = v.w;
            }
        }
        __syncthreads();

        // ---- GEMM1: S[4x4] = sum_k Yt[k][4tr+i] * Xt[k][4tc+j] ----
        float Sa[4][4];
#pragma unroll
        for (int i = 0; i < 4; i++)
#pragma unroll
            for (int j = 0; j < 4; j++) Sa[i][j] = 0.f;

        {
            const float* ya = Yt + 4 * tr;
            const float* xb = Xt + 4 * tc;
#pragma unroll 8
            for (int k = 0; k < Dn; k++) {
                float a0 = ya[k * 65 + 0];
                float a1 = ya[k * 65 + 1];
                float a2 = ya[k * 65 + 2];
                float a3 = ya[k * 65 + 3];
                float b0 = xb[k * 65 + 0];
                float b1 = xb[k * 65 + 1];
                float b2 = xb[k * 65 + 2];
                float b3 = xb[k * 65 + 3];
                Sa[0][0] += a0 * b0; Sa[0][1] += a0 * b1; Sa[0][2] += a0 * b2; Sa[0][3] += a0 * b3;
                Sa[1][0] += a1 * b0; Sa[1][1] += a1 * b1; Sa[1][2] += a1 * b2; Sa[1][3] += a1 * b3;
                Sa[2][0] += a2 * b0; Sa[2][1] += a2 * b1; Sa[2][2] += a2 * b2; Sa[2][3] += a2 * b3;
                Sa[3][0] += a3 * b0; Sa[3][1] += a3 * b1; Sa[3][2] += a3 * b2; Sa[3][3] += a3 * b3;
            }
        }

        // ---- exp + store P^T: Pt[n][m] = exp(S[m][n] - 30) ----
        // Shift by 30 keeps e^s in safe fp32 range for these inputs (|s| <~ 50);
        // softmax is shift-invariant so the result is exact.
#pragma unroll
        for (int j = 0; j < 4; j++)
#pragma unroll
            for (int i = 0; i < 4; i++)
                Pt[(4 * tc + j) * 65 + 4 * tr + i] = __expf(Sa[i][j] - 30.f);

        __syncthreads();

        // ---- den: row sums of P (threads 0..63, row = tid) ----
        if (tid < 64) {
            float dsum = 0.f;
#pragma unroll 8
            for (int n = 0; n < NX; n++) dsum += Pt[n * 65 + tid];
            denAcc += dsum;
        }

        // ---- GEMM2: num[i][j] += sum_n P[4tr+i][n] * X[n][8tc+j] ----
#pragma unroll 4
        for (int n = 0; n < NX; n++) {
            float a0 = Pt[n * 65 + 4 * tr + 0];
            float a1 = Pt[n * 65 + 4 * tr + 1];
            float a2 = Pt[n * 65 + 4 * tr + 2];
            float a3 = Pt[n * 65 + 4 * tr + 3];
            float bb[8];
#pragma unroll
            for (int j = 0; j < 8; j++) bb[j] = Xt[(8 * tc + j) * 65 + n];
#pragma unroll
            for (int j = 0; j < 8; j++) {
                num[0][j] += a0 * bb[j];
                num[1][j] += a1 * bb[j];
                num[2][j] += a2 * bb[j];
                num[3][j] += a3 * bb[j];
            }
        }
    }

    // ---- Epilogue: out[b][d] += (1/Sn) * sum_m num[m][d]/den[m] ----
    __syncthreads();
    if (tid < 64) denSm[tid] = denAcc;
    __syncthreads();

    float o[8];
#pragma unroll
    for (int j = 0; j < 8; j++) o[j] = 0.f;
#pragma unroll
    for (int i = 0; i < 4; i++) {
        float r = 1.f / denSm[4 * tr + i];
#pragma unroll
        for (int j = 0; j < 8; j++) o[j] += num[i][j] * r;
    }

    float* red = Pt;  // reuse (4160 floats >= 16*128)
#pragma unroll
    for (int j = 0; j < 8; j++) red[tr * 128 + 8 * tc + j] = o[j];
    __syncthreads();

    if (tid < Dn) {
        float s2 = 0.f;
#pragma unroll
        for (int t2 = 0; t2 < 16; t2++) s2 += red[t2 * 128 + tid];
        atomicAdd(&outAttn[b * Dn + tid], s2 * (1.f / Sn));
    }
}

// ---------------------------------------------------------------------------
// kernel_launch
// ---------------------------------------------------------------------------
extern "C" void kernel_launch(void* const* d_in, const int* in_sizes, int n_in,
                              void* d_out, int out_size) {
    const float* X = (const float*)d_in[0];  // input_x [B, SX, D]
    const float* Y = (const float*)d_in[1];  // input_y [B, SY, D]
    float* out = (float*)d_out;
    float* outVis  = out;             // [B, SX] = 32768 floats
    float* outAttn = out + Bn * Sn;   // [B, D]  = 2048 floats

    const size_t smem = (size_t)(2 * 128 * 65 + 64 * 65 + 64) * sizeof(float);  // 83456 B
    cudaFuncSetAttribute(attn_kernel, cudaFuncAttributeMaxDynamicSharedMemorySize, (int)smem);

    zero_kernel<<<(Bn * Dn + 255) / 256, 256>>>(outAttn);
    ysum_kernel<<<dim3(16, Bn), 128>>>(Y);
    visual_kernel<<<dim3(16, Bn), 128>>>(X, outVis);
    attn_kernel<<<dim3(Sn / MY, Bn), 256, smem>>>(X, Y, outAttn);
}

// round 5
// speedup vs baseline: 5.1108x; 5.1108x over previous
#include <cuda_runtime.h>
#include <cuda_fp16.h>
#include <math.h>
#include <stdint.h>

// Problem constants
#define Bn 16
#define Sn 2048
#define Dn 128
#define TM 64           // y rows per CTA
#define TN 64           // x cols per tile
#define NT (Sn / TN)    // 32 tiles
#define RS  136         // smem row stride (halves): 272B -> conflict-free ldmatrix
#define RSB 272         // row stride bytes
#define TILE_B (TM * RSB)   // 17408 bytes per 64x128 half tile

// ---------------------------------------------------------------------------
// Global scratch (referenced ONLY from device code — host must never pass
// these as kernel args; the host-side shadow symbol is not the device address)
// ---------------------------------------------------------------------------
__device__ float  g_ysum[Bn * Dn];
__device__ __half g_Yh[Bn * Sn * Dn];
__device__ __half g_Yl[Bn * Sn * Dn];
__device__ __half g_Xh[Bn * Sn * Dn];
__device__ __half g_Xl[Bn * Sn * Dn];

// ---------------------------------------------------------------------------
// Helpers
// ---------------------------------------------------------------------------
__device__ __forceinline__ uint32_t smem_to_u32(const void* p) {
    uint32_t a;
    asm("{ .reg .u64 t; cvta.to.shared.u64 t, %1; cvt.u32.u64 %0, t; }" : "=r"(a) : "l"(p));
    return a;
}

#define CP16(dst, src) \
    asm volatile("cp.async.cg.shared.global [%0], [%1], 16;" :: "r"(dst), "l"(src))
#define CP_COMMIT() asm volatile("cp.async.commit_group;" ::: "memory")
#define CP_WAIT0()  asm volatile("cp.async.wait_group 0;" ::: "memory")

#define LDM4(r, a) \
    asm volatile("ldmatrix.sync.aligned.m8n8.x4.shared.b16 {%0,%1,%2,%3}, [%4];" \
                 : "=r"((r)[0]), "=r"((r)[1]), "=r"((r)[2]), "=r"((r)[3]) : "r"(a))
#define LDM4T(r, a) \
    asm volatile("ldmatrix.sync.aligned.m8n8.x4.trans.shared.b16 {%0,%1,%2,%3}, [%4];" \
                 : "=r"((r)[0]), "=r"((r)[1]), "=r"((r)[2]), "=r"((r)[3]) : "r"(a))

#define MMA16816(c, a, b0, b1) \
    asm volatile("mma.sync.aligned.m16n8k16.row.col.f32.f16.f16.f32 " \
                 "{%0,%1,%2,%3},{%4,%5,%6,%7},{%8,%9},{%0,%1,%2,%3};" \
                 : "+f"((c)[0]), "+f"((c)[1]), "+f"((c)[2]), "+f"((c)[3]) \
                 : "r"((a)[0]), "r"((a)[1]), "r"((a)[2]), "r"((a)[3]), "r"(b0), "r"(b1))

__device__ __forceinline__ uint32_t h2u(float a, float b) {
    __half2 h = __floats2half2_rn(a, b);
    return *reinterpret_cast<uint32_t*>(&h);
}

// ---------------------------------------------------------------------------
// Precompute kernels
// ---------------------------------------------------------------------------
__global__ void zero_kernel(float* __restrict__ outAttn) {
    int t = blockIdx.x * blockDim.x + threadIdx.x;
    if (t < Bn * Dn) { outAttn[t] = 0.f; g_ysum[t] = 0.f; }
}

// fp32 -> (fp16 hi, fp16 lo residual). Globals referenced from DEVICE code.
__global__ void convX_kernel(const float* __restrict__ S) {
    size_t base = ((size_t)blockIdx.y * Sn + (size_t)blockIdx.x * 128) * Dn;
    for (int e = threadIdx.x; e < 128 * Dn; e += 256) {
        float v = S[base + e];
        __half h = __float2half_rn(v);
        g_Xh[base + e] = h;
        g_Xl[base + e] = __float2half_rn(v - __half2float(h));
    }
}

__global__ void convY_kernel(const float* __restrict__ S) {
    size_t base = ((size_t)blockIdx.y * Sn + (size_t)blockIdx.x * 128) * Dn;
    for (int e = threadIdx.x; e < 128 * Dn; e += 256) {
        float v = S[base + e];
        __half h = __float2half_rn(v);
        g_Yh[base + e] = h;
        g_Yl[base + e] = __float2half_rn(v - __half2float(h));
    }
}

__global__ void ysum_kernel(const float* __restrict__ Y) {
    int b = blockIdx.y, chunk = blockIdx.x, d = threadIdx.x;
    const float* base = Y + ((size_t)b * Sn + (size_t)chunk * 128) * Dn + d;
    float s = 0.f;
#pragma unroll 8
    for (int r = 0; r < 128; r++) s += base[(size_t)r * Dn];
    atomicAdd(&g_ysum[b * Dn + d], s);
}

__global__ void visual_kernel(const float* __restrict__ X, float* __restrict__ outVis) {
    __shared__ float yb[Dn];
    int b = blockIdx.y, chunk = blockIdx.x, t = threadIdx.x;
    yb[t] = g_ysum[b * Dn + t];
    __syncthreads();
    int x = chunk * 128 + t;
    const float4* xr = (const float4*)(X + ((size_t)b * Sn + x) * Dn);
    const float4* yv = (const float4*)yb;
    float s = 0.f;
#pragma unroll
    for (int i = 0; i < Dn / 4; i++) {
        float4 a = xr[i]; float4 c = yv[i];
        s += a.x * c.x + a.y * c.y + a.z * c.z + a.w * c.w;
    }
    outVis[(size_t)b * Sn + x] = s * (1.f / Sn);
}

// ---------------------------------------------------------------------------
// Main mma.sync flash-attention kernel.
// 128 threads (4 warps), warp w owns y-rows [w*16, w*16+16) of the CTA tile.
// Smem: Yh @0, Yl @17408, X double-buffer @34816 (each buf: {Xh, Xl} 34816B).
// Total dynamic smem = 6*TILE_B = 104448 B -> 2 CTAs/SM.
// ---------------------------------------------------------------------------
__global__ __launch_bounds__(128, 2)
void attn_mma(float* __restrict__ outAttn) {
    extern __shared__ char sm[];
    const uint32_t sb = smem_to_u32(sm);
    const int tid = threadIdx.x;
    const int lane = tid & 31;
    const int wp = tid >> 5;
    const int b = blockIdx.y;
    const int yt = blockIdx.x;

    const uint32_t YHs = sb;
    const uint32_t YLs = sb + TILE_B;
    const uint32_t XBs = sb + 2 * TILE_B;   // + buf*(2*TILE_B): {Xh, Xl}

    const __half* gyh = g_Yh + ((size_t)b * Sn + (size_t)yt * TM) * Dn;
    const __half* gyl = g_Yl + ((size_t)b * Sn + (size_t)yt * TM) * Dn;
    const __half* gxh = g_Xh + (size_t)b * Sn * Dn;
    const __half* gxl = g_Xl + (size_t)b * Sn * Dn;

    // ---- Prologue: load Y tiles + X tile 0 ----
    {
        for (int e = tid; e < TM * 16; e += 128) {
            int r = e >> 4, c = e & 15;
            uint32_t o = (uint32_t)(r * RSB + c * 16);
            CP16(YHs + o, gyh + r * Dn + c * 8);
            CP16(YLs + o, gyl + r * Dn + c * 8);
            CP16(XBs + o,          gxh + (size_t)r * Dn + c * 8);
            CP16(XBs + TILE_B + o, gxl + (size_t)r * Dn + c * 8);
        }
        CP_COMMIT();
    }
    CP_WAIT0();
    __syncthreads();

    const int g = lane >> 3;   // ldmatrix address group 0..3
    const int li = lane & 7;

    // ---- A fragments (Y), persistent in registers ----
    uint32_t Ah[8][4], Al[8][4];
    {
        uint32_t abase = (uint32_t)((wp * 16 + (g & 1) * 8 + li) * RSB + (g >> 1) * 16);
#pragma unroll
        for (int kf = 0; kf < 8; kf++) {
            LDM4(Ah[kf], YHs + abase + kf * 32);
            LDM4(Al[kf], YLs + abase + kf * 32);
        }
    }

    float num[16][4];
#pragma unroll
    for (int nb = 0; nb < 16; nb++)
#pragma unroll
        for (int j = 0; j < 4; j++) num[nb][j] = 0.f;
    float m0 = -1e30f, m1 = -1e30f;
    float den0 = 0.f, den1 = 0.f;

    // GEMM1 (non-trans) B-frag base; GEMM2 (trans) B-frag base
    const uint32_t b1base = (uint32_t)(((g >> 1) * 8 + li) * RSB + (g & 1) * 16);
    const uint32_t b2base = (uint32_t)(((g & 1) * 8 + li) * RSB + (g >> 1) * 16);

#pragma unroll 1
    for (int t = 0; t < NT; t++) {
        CP_WAIT0();
        __syncthreads();
        if (t + 1 < NT) {
            uint32_t dst = XBs + (uint32_t)((t + 1) & 1) * (2 * TILE_B);
            const __half* xh = gxh + (size_t)(t + 1) * TN * Dn;
            const __half* xl = gxl + (size_t)(t + 1) * TN * Dn;
            for (int e = tid; e < TN * 16; e += 128) {
                int r = e >> 4, c = e & 15;
                uint32_t o = (uint32_t)(r * RSB + c * 16);
                CP16(dst + o,          xh + (size_t)r * Dn + c * 8);
                CP16(dst + TILE_B + o, xl + (size_t)r * Dn + c * 8);
            }
        }
        CP_COMMIT();

        const uint32_t XH = XBs + (uint32_t)(t & 1) * (2 * TILE_B);
        const uint32_t XL = XH + TILE_B;

        // ---- GEMM1: S = Yh*Xh + Yl*Xh + Yh*Xl  (split fp16) ----
        float Sa[8][4];
#pragma unroll
        for (int nb = 0; nb < 8; nb++)
#pragma unroll
            for (int j = 0; j < 4; j++) Sa[nb][j] = 0.f;

#pragma unroll
        for (int nbp = 0; nbp < 4; nbp++) {
#pragma unroll
            for (int kf = 0; kf < 8; kf++) {
                uint32_t off = b1base + (uint32_t)(nbp * 16 * RSB + kf * 32);
                uint32_t bh[4], bl[4];
                LDM4(bh, XH + off);
                LDM4(bl, XL + off);
                MMA16816(Sa[2 * nbp],     Ah[kf], bh[0], bh[1]);
                MMA16816(Sa[2 * nbp + 1], Ah[kf], bh[2], bh[3]);
                MMA16816(Sa[2 * nbp],     Al[kf], bh[0], bh[1]);
                MMA16816(Sa[2 * nbp + 1], Al[kf], bh[2], bh[3]);
                MMA16816(Sa[2 * nbp],     Ah[kf], bl[0], bl[1]);
                MMA16816(Sa[2 * nbp + 1], Ah[kf], bl[2], bl[3]);
            }
        }

        // ---- online max + rescale ----
        float t0 = -1e30f, t1 = -1e30f;
#pragma unroll
        for (int nb = 0; nb < 8; nb++) {
            t0 = fmaxf(t0, fmaxf(Sa[nb][0], Sa[nb][1]));
            t1 = fmaxf(t1, fmaxf(Sa[nb][2], Sa[nb][3]));
        }
        t0 = fmaxf(t0, __shfl_xor_sync(0xffffffffu, t0, 1));
        t0 = fmaxf(t0, __shfl_xor_sync(0xffffffffu, t0, 2));
        t1 = fmaxf(t1, __shfl_xor_sync(0xffffffffu, t1, 1));
        t1 = fmaxf(t1, __shfl_xor_sync(0xffffffffu, t1, 2));
        float mn0 = fmaxf(m0, t0), mn1 = fmaxf(m1, t1);
        float f0 = __expf(m0 - mn0), f1 = __expf(m1 - mn1);
        m0 = mn0; m1 = mn1;
        den0 *= f0; den1 *= f1;
#pragma unroll
        for (int nb = 0; nb < 16; nb++) {
            num[nb][0] *= f0; num[nb][1] *= f0;
            num[nb][2] *= f1; num[nb][3] *= f1;
        }

        // ---- exp + pack P as A-fragments for GEMM2 ----
        uint32_t Pa[4][4];
#pragma unroll
        for (int nb = 0; nb < 8; nb++) {
            float p0 = __expf(Sa[nb][0] - m0);
            float p1 = __expf(Sa[nb][1] - m0);
            float p2 = __expf(Sa[nb][2] - m1);
            float p3 = __expf(Sa[nb][3] - m1);
            den0 += p0 + p1;
            den1 += p2 + p3;
            int kg = nb >> 1;
            if ((nb & 1) == 0) { Pa[kg][0] = h2u(p0, p1); Pa[kg][1] = h2u(p2, p3); }
            else               { Pa[kg][2] = h2u(p0, p1); Pa[kg][3] = h2u(p2, p3); }
        }

        // ---- GEMM2: num += P*Xh + P*Xl  (trans ldmatrix B) ----
#pragma unroll
        for (int nbp = 0; nbp < 8; nbp++) {
#pragma unroll
            for (int kg = 0; kg < 4; kg++) {
                uint32_t off = b2base + (uint32_t)(kg * 16 * RSB + nbp * 32);
                uint32_t bh[4], bl[4];
                LDM4T(bh, XH + off);
                LDM4T(bl, XL + off);
                MMA16816(num[2 * nbp],     Pa[kg], bh[0], bh[1]);
                MMA16816(num[2 * nbp + 1], Pa[kg], bh[2], bh[3]);
                MMA16816(num[2 * nbp],     Pa[kg], bl[0], bl[1]);
                MMA16816(num[2 * nbp + 1], Pa[kg], bl[2], bl[3]);
            }
        }
    }

    // ---- Epilogue ----
    den0 += __shfl_xor_sync(0xffffffffu, den0, 1);
    den0 += __shfl_xor_sync(0xffffffffu, den0, 2);
    den1 += __shfl_xor_sync(0xffffffffu, den1, 1);
    den1 += __shfl_xor_sync(0xffffffffu, den1, 2);
    float rd0 = 1.f / den0, rd1 = 1.f / den1;

    float* epi = (float*)(sm + 2 * TILE_B);   // reuse X buffer 0 region
    __syncthreads();
    if (tid < Dn) epi[tid] = 0.f;
    __syncthreads();

    int c0 = 2 * (lane & 3);
#pragma unroll
    for (int nb = 0; nb < 16; nb++) {
        atomicAdd(&epi[nb * 8 + c0],     num[nb][0] * rd0 + num[nb][2] * rd1);
        atomicAdd(&epi[nb * 8 + c0 + 1], num[nb][1] * rd0 + num[nb][3] * rd1);
    }
    __syncthreads();

    if (tid < Dn) atomicAdd(&outAttn[b * Dn + tid], epi[tid] * (1.f / Sn));
}

// ---------------------------------------------------------------------------
// kernel_launch
// ---------------------------------------------------------------------------
extern "C" void kernel_launch(void* const* d_in, const int* in_sizes, int n_in,
                              void* d_out, int out_size) {
    const float* X = (const float*)d_in[0];  // input_x [B, SX, D]
    const float* Y = (const float*)d_in[1];  // input_y [B, SY, D]
    float* out = (float*)d_out;
    float* outVis  = out;             // [B, SX]
    float* outAttn = out + Bn * Sn;   // [B, D]

    cudaFuncSetAttribute(attn_mma, cudaFuncAttributeMaxDynamicSharedMemorySize, 6 * TILE_B);

    zero_kernel<<<(Bn * Dn + 255) / 256, 256>>>(outAttn);
    convX_kernel<<<dim3(16, Bn), 256>>>(X);
    convY_kernel<<<dim3(16, Bn), 256>>>(Y);
    ysum_kernel<<<dim3(16, Bn), 128>>>(Y);
    visual_kernel<<<dim3(16, Bn), 128>>>(X, outVis);
    attn_mma<<<dim3(Sn / TM, Bn), 128, 6 * TILE_B>>>(outAttn);
}

// round 7
// speedup vs baseline: 5.9787x; 1.1698x over previous
#include <cuda_runtime.h>
#include <cuda_fp16.h>
#include <math.h>
#include <stdint.h>

// Problem constants
#define Bn 16
#define Sn 2048
#define Dn 128
#define TM 64           // y rows per CTA
#define TN 64           // x cols per tile
#define NT (Sn / TN)    // 32 tiles
#define RSB 272         // smem row stride bytes (136 halves): conflict-free ldmatrix
#define TILE_B (TM * RSB)   // 17408 bytes per 64x128 half tile

// ---------------------------------------------------------------------------
// Global scratch (referenced ONLY from device code)
// ---------------------------------------------------------------------------
__device__ float  g_ysum[Bn * Dn];
__device__ __half g_Yh[Bn * Sn * Dn];
__device__ __half g_Xh[Bn * Sn * Dn];
__device__ __half g_Xl[Bn * Sn * Dn];

// ---------------------------------------------------------------------------
// Helpers
// ---------------------------------------------------------------------------
__device__ __forceinline__ uint32_t smem_to_u32(const void* p) {
    uint32_t a;
    asm("{ .reg .u64 t; cvta.to.shared.u64 t, %1; cvt.u32.u64 %0, t; }" : "=r"(a) : "l"(p));
    return a;
}

#define CP16(dst, src) \
    asm volatile("cp.async.cg.shared.global [%0], [%1], 16;" :: "r"(dst), "l"(src))
#define CP_COMMIT() asm volatile("cp.async.commit_group;" ::: "memory")
#define CP_WAIT0()  asm volatile("cp.async.wait_group 0;" ::: "memory")

#define LDM4(r, a) \
    asm volatile("ldmatrix.sync.aligned.m8n8.x4.shared.b16 {%0,%1,%2,%3}, [%4];" \
                 : "=r"((r)[0]), "=r"((r)[1]), "=r"((r)[2]), "=r"((r)[3]) : "r"(a))
#define LDM4T(r, a) \
    asm volatile("ldmatrix.sync.aligned.m8n8.x4.trans.shared.b16 {%0,%1,%2,%3}, [%4];" \
                 : "=r"((r)[0]), "=r"((r)[1]), "=r"((r)[2]), "=r"((r)[3]) : "r"(a))

#define MMA16816(c, a, b0, b1) \
    asm volatile("mma.sync.aligned.m16n8k16.row.col.f32.f16.f16.f32 " \
                 "{%0,%1,%2,%3},{%4,%5,%6,%7},{%8,%9},{%0,%1,%2,%3};" \
                 : "+f"((c)[0]), "+f"((c)[1]), "+f"((c)[2]), "+f"((c)[3]) \
                 : "r"((a)[0]), "r"((a)[1]), "r"((a)[2]), "r"((a)[3]), "r"(b0), "r"(b1))

__device__ __forceinline__ uint32_t h2u(float a, float b) {
    __half2 h = __floats2half2_rn(a, b);
    return *reinterpret_cast<uint32_t*>(&h);
}

// ---------------------------------------------------------------------------
// Precompute kernels
// ---------------------------------------------------------------------------
__global__ void zero_kernel(float* __restrict__ outAttn) {
    int t = blockIdx.x * blockDim.x + threadIdx.x;
    if (t < Bn * Dn) { outAttn[t] = 0.f; g_ysum[t] = 0.f; }
}

// X: fp32 -> (fp16 hi, fp16 lo residual)
__global__ void convX_kernel(const float* __restrict__ S) {
    size_t base = ((size_t)blockIdx.y * Sn + (size_t)blockIdx.x * 128) * Dn;
    for (int e = threadIdx.x; e < 128 * Dn; e += 256) {
        float v = S[base + e];
        __half h = __float2half_rn(v);
        g_Xh[base + e] = h;
        g_Xl[base + e] = __float2half_rn(v - __half2float(h));
    }
}

// Y: fp32 -> fp16 hi only, fused with column-sum for attention_visual.
// Each thread's elements e = tid + k*256 share a fixed d = tid & 127.
__global__ void convY_kernel(const float* __restrict__ S) {
    __shared__ float red[256];
    int b = blockIdx.y;
    size_t base = ((size_t)b * Sn + (size_t)blockIdx.x * 128) * Dn;
    int tid = threadIdx.x;
    float part = 0.f;
    for (int e = tid; e < 128 * Dn; e += 256) {
        float v = S[base + e];
        g_Yh[base + e] = __float2half_rn(v);
        part += v;
    }
    red[tid] = part;
    __syncthreads();
    if (tid < 128) atomicAdd(&g_ysum[b * Dn + tid], red[tid] + red[tid + 128]);
}

// attention_visual: warp-per-x-row, lane-strided float4 (coalesced) + shfl reduce.
__global__ void visual_kernel(const float* __restrict__ X, float* __restrict__ outVis) {
    __shared__ float yb[Dn];
    int b = blockIdx.y, chunk = blockIdx.x, tid = threadIdx.x;
    int lane = tid & 31, wp = tid >> 5;
    if (tid < Dn) yb[tid] = g_ysum[b * Dn + tid];
    __syncthreads();

    float4 yv = ((const float4*)yb)[lane];
#pragma unroll 4
    for (int it = 0; it < 32; it++) {
        int x = chunk * 128 + wp * 32 + it;
        float4 a = ((const float4*)(X + ((size_t)b * Sn + x) * Dn))[lane];
        float s = a.x * yv.x + a.y * yv.y + a.z * yv.z + a.w * yv.w;
        s += __shfl_xor_sync(0xffffffffu, s, 16);
        s += __shfl_xor_sync(0xffffffffu, s, 8);
        s += __shfl_xor_sync(0xffffffffu, s, 4);
        s += __shfl_xor_sync(0xffffffffu, s, 2);
        s += __shfl_xor_sync(0xffffffffu, s, 1);
        if (lane == 0) outVis[(size_t)b * Sn + x] = s * (1.f / Sn);
    }
}

// ---------------------------------------------------------------------------
// Main mma.sync flash-attention kernel.
// 128 threads (4 warps), warp w owns y-rows [w*16, w*16+16) of the CTA tile.
// S = Yh*(Xh+Xl) = Yh*X exactly (fp16 products exact in fp32); the only
// score error is (y - yh).x which is independent across y rows and shrinks
// ~45x in the mean over Sn rows.
// Smem: Yh @0, X double-buffer @TILE_B (each buf: {Xh, Xl} 2*TILE_B).
// Total dynamic smem = 5*TILE_B = 87040 B -> 2 CTAs/SM.
// ---------------------------------------------------------------------------
__global__ __launch_bounds__(128, 2)
void attn_mma(float* __restrict__ outAttn) {
    extern __shared__ char sm[];
    const uint32_t sb = smem_to_u32(sm);
    const int tid = threadIdx.x;
    const int lane = tid & 31;
    const int wp = tid >> 5;
    const int b = blockIdx.y;
    const int yt = blockIdx.x;

    const uint32_t YHs = sb;
    const uint32_t XBs = sb + TILE_B;   // + buf*(2*TILE_B): {Xh, Xl}

    const __half* gyh = g_Yh + ((size_t)b * Sn + (size_t)yt * TM) * Dn;
    const __half* gxh = g_Xh + (size_t)b * Sn * Dn;
    const __half* gxl = g_Xl + (size_t)b * Sn * Dn;

    // ---- Prologue: load Y tile + X tile 0 ----
    {
        for (int e = tid; e < TM * 16; e += 128) {
            int r = e >> 4, c = e & 15;
            uint32_t o = (uint32_t)(r * RSB + c * 16);
            CP16(YHs + o, gyh + r * Dn + c * 8);
            CP16(XBs + o,          gxh + (size_t)r * Dn + c * 8);
            CP16(XBs + TILE_B + o, gxl + (size_t)r * Dn + c * 8);
        }
        CP_COMMIT();
    }
    CP_WAIT0();
    __syncthreads();

    const int g = lane >> 3;   // ldmatrix address group 0..3
    const int li = lane & 7;

    // ---- A fragments (Yh), persistent in registers ----
    uint32_t Ah[8][4];
    {
        uint32_t abase = (uint32_t)((wp * 16 + (g & 1) * 8 + li) * RSB + (g >> 1) * 16);
#pragma unroll
        for (int kf = 0; kf < 8; kf++) LDM4(Ah[kf], YHs + abase + kf * 32);
    }

    float num[16][4];
#pragma unroll
    for (int nb = 0; nb < 16; nb++)
#pragma unroll
        for (int j = 0; j < 4; j++) num[nb][j] = 0.f;
    float m0 = -1e30f, m1 = -1e30f;
    float den0 = 0.f, den1 = 0.f;

    // GEMM1 (non-trans) B-frag base; GEMM2 (trans) B-frag base
    const uint32_t b1base = (uint32_t)(((g >> 1) * 8 + li) * RSB + (g & 1) * 16);
    const uint32_t b2base = (uint32_t)(((g & 1) * 8 + li) * RSB + (g >> 1) * 16);

#pragma unroll 1
    for (int t = 0; t < NT; t++) {
        CP_WAIT0();
        __syncthreads();
        if (t + 1 < NT) {
            uint32_t dst = XBs + (uint32_t)((t + 1) & 1) * (2 * TILE_B);
            const __half* xh = gxh + (size_t)(t + 1) * TN * Dn;
            const __half* xl = gxl + (size_t)(t + 1) * TN * Dn;
            for (int e = tid; e < TN * 16; e += 128) {
                int r = e >> 4, c = e & 15;
                uint32_t o = (uint32_t)(r * RSB + c * 16);
                CP16(dst + o,          xh + (size_t)r * Dn + c * 8);
                CP16(dst + TILE_B + o, xl + (size_t)r * Dn + c * 8);
            }
        }
        CP_COMMIT();

        const uint32_t XH = XBs + (uint32_t)(t & 1) * (2 * TILE_B);
        const uint32_t XL = XH + TILE_B;

        // ---- GEMM1: S = Yh*Xh + Yh*Xl  (= Yh*X exactly) ----
        float Sa[8][4];
#pragma unroll
        for (int nb = 0; nb < 8; nb++)
#pragma unroll
            for (int j = 0; j < 4; j++) Sa[nb][j] = 0.f;

#pragma unroll
        for (int nbp = 0; nbp < 4; nbp++) {
#pragma unroll
            for (int kf = 0; kf < 8; kf++) {
                uint32_t off = b1base + (uint32_t)(nbp * 16 * RSB + kf * 32);
                uint32_t bh[4], bl[4];
                LDM4(bh, XH + off);
                LDM4(bl, XL + off);
                MMA16816(Sa[2 * nbp],     Ah[kf], bh[0], bh[1]);
                MMA16816(Sa[2 * nbp + 1], Ah[kf], bh[2], bh[3]);
                MMA16816(Sa[2 * nbp],     Ah[kf], bl[0], bl[1]);
                MMA16816(Sa[2 * nbp + 1], Ah[kf], bl[2], bl[3]);
            }
        }

        // ---- online max + rescale ----
        float t0 = -1e30f, t1 = -1e30f;
#pragma unroll
        for (int nb = 0; nb < 8; nb++) {
            t0 = fmaxf(t0, fmaxf(Sa[nb][0], Sa[nb][1]));
            t1 = fmaxf(t1, fmaxf(Sa[nb][2], Sa[nb][3]));
        }
        t0 = fmaxf(t0, __shfl_xor_sync(0xffffffffu, t0, 1));
        t0 = fmaxf(t0, __shfl_xor_sync(0xffffffffu, t0, 2));
        t1 = fmaxf(t1, __shfl_xor_sync(0xffffffffu, t1, 1));
        t1 = fmaxf(t1, __shfl_xor_sync(0xffffffffu, t1, 2));
        float mn0 = fmaxf(m0, t0), mn1 = fmaxf(m1, t1);
        float f0 = __expf(m0 - mn0), f1 = __expf(m1 - mn1);
        m0 = mn0; m1 = mn1;
        den0 *= f0; den1 *= f1;
#pragma unroll
        for (int nb = 0; nb < 16; nb++) {
            num[nb][0] *= f0; num[nb][1] *= f0;
            num[nb][2] *= f1; num[nb][3] *= f1;
        }

        // ---- exp + pack P as A-fragments for GEMM2 ----
        uint32_t Pa[4][4];
#pragma unroll
        for (int nb = 0; nb < 8; nb++) {
            float p0 = __expf(Sa[nb][0] - m0);
            float p1 = __expf(Sa[nb][1] - m0);
            float p2 = __expf(Sa[nb][2] - m1);
            float p3 = __expf(Sa[nb][3] - m1);
            den0 += p0 + p1;
            den1 += p2 + p3;
            int kg = nb >> 1;
            if ((nb & 1) == 0) { Pa[kg][0] = h2u(p0, p1); Pa[kg][1] = h2u(p2, p3); }
            else               { Pa[kg][2] = h2u(p0, p1); Pa[kg][3] = h2u(p2, p3); }
        }

        // ---- GEMM2: num += P*Xh + P*Xl  (trans ldmatrix B) ----
#pragma unroll
        for (int nbp = 0; nbp < 8; nbp++) {
#pragma unroll
            for (int kg = 0; kg < 4; kg++) {
                uint32_t off = b2base + (uint32_t)(kg * 16 * RSB + nbp * 32);
                uint32_t bh[4], bl[4];
                LDM4T(bh, XH + off);
                LDM4T(bl, XL + off);
                MMA16816(num[2 * nbp],     Pa[kg], bh[0], bh[1]);
                MMA16816(num[2 * nbp + 1], Pa[kg], bh[2], bh[3]);
                MMA16816(num[2 * nbp],     Pa[kg], bl[0], bl[1]);
                MMA16816(num[2 * nbp + 1], Pa[kg], bl[2], bl[3]);
            }
        }
    }

    // ---- Epilogue ----
    den0 += __shfl_xor_sync(0xffffffffu, den0, 1);
    den0 += __shfl_xor_sync(0xffffffffu, den0, 2);
    den1 += __shfl_xor_sync(0xffffffffu, den1, 1);
    den1 += __shfl_xor_sync(0xffffffffu, den1, 2);
    float rd0 = 1.f / den0, rd1 = 1.f / den1;

    float* epi = (float*)(sm + TILE_B);   // reuse X buffer region (loop done)
    __syncthreads();
    if (tid < Dn) epi[tid] = 0.f;
    __syncthreads();

    int c0 = 2 * (lane & 3);
#pragma unroll
    for (int nb = 0; nb < 16; nb++) {
        atomicAdd(&epi[nb * 8 + c0],     num[nb][0] * rd0 + num[nb][2] * rd1);
        atomicAdd(&epi[nb * 8 + c0 + 1], num[nb][1] * rd0 + num[nb][3] * rd1);
    }
    __syncthreads();

    if (tid < Dn) atomicAdd(&outAttn[b * Dn + tid], epi[tid] * (1.f / Sn));
}

// ---------------------------------------------------------------------------
// kernel_launch
// ---------------------------------------------------------------------------
extern "C" void kernel_launch(void* const* d_in, const int* in_sizes, int n_in,
                              void* d_out, int out_size) {
    const float* X = (const float*)d_in[0];  // input_x [B, SX, D]
    const float* Y = (const float*)d_in[1];  // input_y [B, SY, D]
    float* out = (float*)d_out;
    float* outVis  = out;             // [B, SX]
    float* outAttn = out + Bn * Sn;   // [B, D]

    cudaFuncSetAttribute(attn_mma, cudaFuncAttributeMaxDynamicSharedMemorySize, 5 * TILE_B);

    zero_kernel<<<(Bn * Dn + 255) / 256, 256>>>(outAttn);
    convX_kernel<<<dim3(16, Bn), 256>>>(X);
    convY_kernel<<<dim3(16, Bn), 256>>>(Y);   // also produces g_ysum
    visual_kernel<<<dim3(16, Bn), 128>>>(X, outVis);
    attn_mma<<<dim3(Sn / TM, Bn), 128, 5 * TILE_B>>>(outAttn);
}